// round 6
// baseline (speedup 1.0000x reference)
#include <cuda_runtime.h>
#include <math.h>

// ---------------------------------------------------------------------------
// DOSAConLoss — single-launch, hybrid reduction version.
//
// loss_loc factorizes (reference broadcasts (N,1)/(N,) -> (N,N) mean):
//   loss_loc = (Sum_i dw_i*hw_i*(1-ciou_i)^2.5) * (Sum_j 1/(area_j+1e-7)) / N^2
//
// 16 blocks x 512 threads. Each warp: 32 boxes (1/lane) + at most one pair
// (pairs striped across blocks so no block is pair-heavy). Warp shuffle
// reduce -> fire-and-forget RED.ADD into 3 global scalars (no partial
// arrays). Completion: __syncthreads then ONE acq_rel counter bump per
// block (16 same-address atomics, not 256 — R5's regression source).
// Last block's thread 0 finalizes and resets (graph-replayable).
// ---------------------------------------------------------------------------

#define EPSF        1e-7f
#define ALPHA_C     1.2f
#define TAU_C       0.3f
#define DELTA_C     1.0f
#define FOUR_PI2    0.40528473456935108577f   // 4/pi^2

#define TPB           512
#define WARPS_PER_BLK (TPB / 32)

__device__ float g_accA = 0.0f;        // Σ dw*hw*(1-ciou)^2.5
__device__ float g_accB = 0.0f;        // Σ 1/(area+1e-7)
__device__ float g_accC = 0.0f;        // Σ masked pair loss
__device__ unsigned int g_done = 0;    // block completion counter

__device__ __forceinline__ unsigned int atomic_inc_acq_rel(unsigned int* p) {
    unsigned int prev;
    asm volatile("atom.acq_rel.gpu.add.u32 %0, [%1], 1;"
                 : "=r"(prev) : "l"(p) : "memory");
    return prev;
}

__device__ __forceinline__ float ld_acquire_f(const float* p) {
    float v;
    asm volatile("ld.acquire.gpu.f32 %0, [%1];" : "=f"(v) : "l"(p) : "memory");
    return v;
}

__global__ __launch_bounds__(TPB)
void dosa_hybrid_kernel(const float4* __restrict__ pred,
                        const float4* __restrict__ tgt,
                        const float*  __restrict__ emb,
                        const float*  __restrict__ dens,
                        const int2*   __restrict__ idx,
                        float* __restrict__ out,
                        int N, int D, int P, int nblocks,
                        float invN2, float pairScale) {
    int lane      = threadIdx.x & 31;
    int warpInBlk = threadIdx.x >> 5;

    // pairs striped across blocks: block b gets pairs {b, b+nblocks, ...},
    // each on a distinct warp -> balanced block finish times
    int p = warpInBlk * nblocks + blockIdx.x;
    bool isPair = (p < P);
    int2 ij = make_int2(0, 0);
    if (isPair) ij = idx[p];           // issue earliest (longest dep chain)

    // ---- localization: one box per lane ----
    float accA = 0.0f, accB = 0.0f;
    int i = blockIdx.x * TPB + threadIdx.x;
    if (i < N) {
        float4 b1 = pred[i];
        float4 b2 = tgt[i];
        float dv  = dens[i];

        float w1 = b1.z, h1 = b1.w, w2 = b2.z, h2 = b2.w;
        float b1x1 = b1.x - w1 * 0.5f, b1x2 = b1.x + w1 * 0.5f;
        float b1y1 = b1.y - h1 * 0.5f, b1y2 = b1.y + h1 * 0.5f;
        float b2x1 = b2.x - w2 * 0.5f, b2x2 = b2.x + w2 * 0.5f;
        float b2y1 = b2.y - h2 * 0.5f, b2y2 = b2.y + h2 * 0.5f;

        float iw = fmaxf(fminf(b1x2, b2x2) - fmaxf(b1x1, b2x1), 0.0f);
        float ih = fmaxf(fminf(b1y2, b2y2) - fmaxf(b1y1, b2y1), 0.0f);
        float inter = iw * ih;
        float uni   = w1 * h1 + w2 * h2 - inter + EPSF;
        float iou   = __fdividef(inter, uni);

        float cw = fmaxf(b1x2, b2x2) - fminf(b1x1, b2x1);
        float ch = fmaxf(b1y2, b2y2) - fminf(b1y1, b2y1);
        float c2 = cw * cw + ch * ch + EPSF;

        float dx = b2x1 + b2x2 - b1x1 - b1x2;
        float dy = b2y1 + b2y2 - b1y1 - b1y2;
        float rho2 = (dx * dx + dy * dy) * 0.25f;

        float dat = atanf(__fdividef(w2, h2)) - atanf(__fdividef(w1, h1));
        float v   = FOUR_PI2 * dat * dat;
        float alpha = __fdividef(v, v - iou + (1.0f + EPSF));
        float ciou = iou - (__fdividef(rho2, c2) + v * alpha);

        float t  = 1.0f - ciou;                   // >= 0
        float pw = t * t * sqrtf(t);              // t^2.5
        float dw = fmaf(ALPHA_C, dv, 1.0f);
        float hw = __fdividef(1.0f, 1.0f + __expf(-5.0f * (0.5f - ciou)));
        accA = dw * hw * pw;
        accB = __fdividef(1.0f, w2 * h2 + 1e-7f);
    }

    // ---- warp reduce loc partials -> fire-and-forget REDs ----
    #pragma unroll
    for (int off = 16; off > 0; off >>= 1) {
        accA += __shfl_down_sync(0xffffffffu, accA, off);
        accB += __shfl_down_sync(0xffffffffu, accB, off);
    }
    if (lane == 0) {
        atomicAdd(&g_accA, accA);                 // RED.ADD (no return)
        atomicAdd(&g_accB, accB);
    }

    // ---- pair term (idx arrived during loc math) ----
    if (isPair) {
        int pi = ij.x, pj = ij.y;
        float4 bi = pred[pi];
        float4 bj = pred[pj];
        const float4* ei = (const float4*)(emb + (size_t)pi * D);
        const float4* ej = (const float4*)(emb + (size_t)pj * D);
        int D4 = D >> 2;
        float s = 0.0f;
        for (int c = lane; c < D4; c += 32) {
            float4 u = ei[c];
            float4 v = ej[c];
            float d0 = u.x - v.x, d1 = u.y - v.y;
            float d2 = u.z - v.z, d3 = u.w - v.w;
            s = fmaf(d0, d0, s); s = fmaf(d1, d1, s);
            s = fmaf(d2, d2, s); s = fmaf(d3, d3, s);
        }
        #pragma unroll
        for (int off = 16; off > 0; off >>= 1)
            s += __shfl_down_sync(0xffffffffu, s, off);

        float a_x1 = bi.x - bi.z * 0.5f, a_x2 = bi.x + bi.z * 0.5f;
        float a_y1 = bi.y - bi.w * 0.5f, a_y2 = bi.y + bi.w * 0.5f;
        float b_x1 = bj.x - bj.z * 0.5f, b_x2 = bj.x + bj.z * 0.5f;
        float b_y1 = bj.y - bj.w * 0.5f, b_y2 = bj.y + bj.w * 0.5f;
        float iw = fmaxf(fminf(a_x2, b_x2) - fmaxf(a_x1, b_x1), 0.0f);
        float ih = fmaxf(fminf(a_y2, b_y2) - fmaxf(a_y1, b_y1), 0.0f);
        float inter = iw * ih;
        float uni = bi.z * bi.w + bj.z * bj.w - inter + EPSF;
        float piou = __fdividef(inter, uni);

        if (lane == 0 && piou > TAU_C) {
            float d = sqrtf(s);
            float t = fmaxf(DELTA_C - d, 0.0f);
            if (t > 0.0f) atomicAdd(&g_accC, t * t);
        }
    }

    // ---- block completion: hb edge from all warps, then ONE bump ----
    __syncthreads();
    if (threadIdx.x != 0) return;

    unsigned int prev = atomic_inc_acq_rel(&g_done);
    if (prev != (unsigned int)(nblocks - 1)) return;

    // last block: acquire-load the three scalars, combine, reset
    float a = ld_acquire_f(&g_accA);
    float b = ld_acquire_f(&g_accB);
    float c = ld_acquire_f(&g_accC);
    out[0] = a * b * invN2 + c * pairScale;
    g_accA = 0.0f;
    g_accB = 0.0f;
    g_accC = 0.0f;
    g_done = 0;                            // reset for next graph replay
}

extern "C" void kernel_launch(void* const* d_in, const int* in_sizes, int n_in,
                              void* d_out, int out_size) {
    const float4* pred = (const float4*)d_in[0];
    const float4* tgt  = (const float4*)d_in[1];
    const float*  emb  = (const float*)d_in[2];
    const float*  dens = (const float*)d_in[3];
    const int2*   idx  = (const int2*)d_in[4];
    float* out = (float*)d_out;

    int N = in_sizes[0] / 4;
    int D = in_sizes[2] / N;
    int P = in_sizes[4] / 2;

    int blocks = (N + TPB - 1) / TPB;             // 16
    // ensure enough warp slots for all pairs (P <= blocks * WARPS_PER_BLK)
    int slots = blocks * WARPS_PER_BLK;
    if (slots < P) blocks = (P + WARPS_PER_BLK - 1) / WARPS_PER_BLK;

    float invN2 = 1.0f / ((float)N * (float)N);
    float pairScale = 0.5f / ((float)P + 1e-7f);

    dosa_hybrid_kernel<<<blocks, TPB>>>(pred, tgt, emb, dens, idx, out,
                                        N, D, P, blocks, invN2, pairScale);
}

// round 7
// speedup vs baseline: 1.0036x; 1.0036x over previous
#include <cuda_runtime.h>
#include <math.h>

// ---------------------------------------------------------------------------
// DOSAConLoss — single-launch, dedicated-pair-warp version.
//
// loss_loc factorizes (reference broadcasts (N,1)/(N,) -> (N,N) mean):
//   loss_loc = (Sum_i dw_i*hw_i*(1-ciou_i)^2.5) * (Sum_j 1/(area_j+1e-7)) / N^2
//
// 16 blocks x 736 threads (23 warps):
//   warps 0-15 : loc, one box per thread (512 boxes/block, 8192 total)
//   warps 16-22: pair, one pair per warp (p = (w-16)*16 + blockIdx, 112>=100)
// Pair warps start their idx->emb dependent chain at cycle 0 (nothing
// precedes the gather). Warp shuffle reduce -> fire-and-forget RED.ADD into
// 3 global scalars. Completion: __syncthreads + ONE acq_rel bump per block
// (16 same-address atomics). Last block's thread 0 finalizes and resets.
// ---------------------------------------------------------------------------

#define EPSF        1e-7f
#define ALPHA_C     1.2f
#define TAU_C       0.3f
#define DELTA_C     1.0f
#define FOUR_PI2    0.40528473456935108577f   // 4/pi^2

#define TPB         736          // 23 warps: 16 loc + 7 pair
#define LOC_THREADS 512

__device__ float g_accA = 0.0f;        // Σ dw*hw*(1-ciou)^2.5
__device__ float g_accB = 0.0f;        // Σ 1/(area+1e-7)
__device__ float g_accC = 0.0f;        // Σ masked pair loss
__device__ unsigned int g_done = 0;    // block completion counter

__device__ __forceinline__ unsigned int atomic_inc_acq_rel(unsigned int* p) {
    unsigned int prev;
    asm volatile("atom.acq_rel.gpu.add.u32 %0, [%1], 1;"
                 : "=r"(prev) : "l"(p) : "memory");
    return prev;
}

__device__ __forceinline__ float ld_acquire_f(const float* p) {
    float v;
    asm volatile("ld.acquire.gpu.f32 %0, [%1];" : "=f"(v) : "l"(p) : "memory");
    return v;
}

__global__ __launch_bounds__(TPB)
void dosa_split_kernel(const float4* __restrict__ pred,
                       const float4* __restrict__ tgt,
                       const float*  __restrict__ emb,
                       const float*  __restrict__ dens,
                       const int2*   __restrict__ idx,
                       float* __restrict__ out,
                       int N, int D, int P, int nblocks,
                       float invN2, float pairScale) {
    int lane = threadIdx.x & 31;
    int warp = threadIdx.x >> 5;

    if (warp >= 16) {
        // ================= dedicated pair warps =================
        // Chain starts immediately: idx -> pred/emb gather -> reduce.
        int p = (warp - 16) * nblocks + blockIdx.x;
        if (p < P) {
            int2 ij = idx[p];
            int pi = ij.x, pj = ij.y;

            const float4* ei = (const float4*)(emb + (size_t)pi * D);
            const float4* ej = (const float4*)(emb + (size_t)pj * D);
            float4 bi = pred[pi];
            float4 bj = pred[pj];

            int D4 = D >> 2;                      // 64
            float s = 0.0f;
            for (int c = lane; c < D4; c += 32) { // 2 iterations at D=256
                float4 u = ei[c];
                float4 v = ej[c];
                float d0 = u.x - v.x, d1 = u.y - v.y;
                float d2 = u.z - v.z, d3 = u.w - v.w;
                s = fmaf(d0, d0, s); s = fmaf(d1, d1, s);
                s = fmaf(d2, d2, s); s = fmaf(d3, d3, s);
            }
            #pragma unroll
            for (int off = 16; off > 0; off >>= 1)
                s += __shfl_down_sync(0xffffffffu, s, off);

            if (lane == 0) {
                float a_x1 = bi.x - bi.z * 0.5f, a_x2 = bi.x + bi.z * 0.5f;
                float a_y1 = bi.y - bi.w * 0.5f, a_y2 = bi.y + bi.w * 0.5f;
                float b_x1 = bj.x - bj.z * 0.5f, b_x2 = bj.x + bj.z * 0.5f;
                float b_y1 = bj.y - bj.w * 0.5f, b_y2 = bj.y + bj.w * 0.5f;
                float iw = fmaxf(fminf(a_x2, b_x2) - fmaxf(a_x1, b_x1), 0.0f);
                float ih = fmaxf(fminf(a_y2, b_y2) - fmaxf(a_y1, b_y1), 0.0f);
                float inter = iw * ih;
                float uni = bi.z * bi.w + bj.z * bj.w - inter + EPSF;
                float piou = __fdividef(inter, uni);
                if (piou > TAU_C) {
                    float d = sqrtf(s);
                    float t = fmaxf(DELTA_C - d, 0.0f);
                    if (t > 0.0f) atomicAdd(&g_accC, t * t);
                }
            }
        }
    } else {
        // ================= loc warps: one box per thread =================
        float accA = 0.0f, accB = 0.0f;
        int i = blockIdx.x * LOC_THREADS + threadIdx.x;
        if (i < N) {
            float4 b1 = pred[i];
            float4 b2 = tgt[i];
            float dv  = dens[i];

            float w1 = b1.z, h1 = b1.w, w2 = b2.z, h2 = b2.w;
            float b1x1 = b1.x - w1 * 0.5f, b1x2 = b1.x + w1 * 0.5f;
            float b1y1 = b1.y - h1 * 0.5f, b1y2 = b1.y + h1 * 0.5f;
            float b2x1 = b2.x - w2 * 0.5f, b2x2 = b2.x + w2 * 0.5f;
            float b2y1 = b2.y - h2 * 0.5f, b2y2 = b2.y + h2 * 0.5f;

            float iw = fmaxf(fminf(b1x2, b2x2) - fmaxf(b1x1, b2x1), 0.0f);
            float ih = fmaxf(fminf(b1y2, b2y2) - fmaxf(b1y1, b2y1), 0.0f);
            float inter = iw * ih;
            float uni   = w1 * h1 + w2 * h2 - inter + EPSF;
            float iou   = __fdividef(inter, uni);

            float cw = fmaxf(b1x2, b2x2) - fminf(b1x1, b2x1);
            float ch = fmaxf(b1y2, b2y2) - fminf(b1y1, b2y1);
            float c2 = cw * cw + ch * ch + EPSF;

            float dx = b2x1 + b2x2 - b1x1 - b1x2;
            float dy = b2y1 + b2y2 - b1y1 - b1y2;
            float rho2 = (dx * dx + dy * dy) * 0.25f;

            float dat = atanf(__fdividef(w2, h2)) - atanf(__fdividef(w1, h1));
            float v   = FOUR_PI2 * dat * dat;
            float alpha = __fdividef(v, v - iou + (1.0f + EPSF));
            float ciou = iou - (__fdividef(rho2, c2) + v * alpha);

            float t  = 1.0f - ciou;                   // >= 0
            float pw = t * t * sqrtf(t);              // t^2.5
            float dw = fmaf(ALPHA_C, dv, 1.0f);
            float hw = __fdividef(1.0f, 1.0f + __expf(-5.0f * (0.5f - ciou)));
            accA = dw * hw * pw;
            accB = __fdividef(1.0f, w2 * h2 + 1e-7f);
        }
        #pragma unroll
        for (int off = 16; off > 0; off >>= 1) {
            accA += __shfl_down_sync(0xffffffffu, accA, off);
            accB += __shfl_down_sync(0xffffffffu, accB, off);
        }
        if (lane == 0) {
            atomicAdd(&g_accA, accA);                 // RED.ADD (no return)
            atomicAdd(&g_accB, accB);
        }
    }

    // ---- block completion: hb edge from all warps, then ONE bump ----
    __syncthreads();
    if (threadIdx.x != 0) return;

    unsigned int prev = atomic_inc_acq_rel(&g_done);
    if (prev != (unsigned int)(nblocks - 1)) return;

    // last block: acquire-load the three scalars, combine, reset
    float a = ld_acquire_f(&g_accA);
    float b = ld_acquire_f(&g_accB);
    float c = ld_acquire_f(&g_accC);
    out[0] = a * b * invN2 + c * pairScale;
    g_accA = 0.0f;
    g_accB = 0.0f;
    g_accC = 0.0f;
    g_done = 0;                            // reset for next graph replay
}

extern "C" void kernel_launch(void* const* d_in, const int* in_sizes, int n_in,
                              void* d_out, int out_size) {
    const float4* pred = (const float4*)d_in[0];
    const float4* tgt  = (const float4*)d_in[1];
    const float*  emb  = (const float*)d_in[2];
    const float*  dens = (const float*)d_in[3];
    const int2*   idx  = (const int2*)d_in[4];
    float* out = (float*)d_out;

    int N = in_sizes[0] / 4;
    int D = in_sizes[2] / N;
    int P = in_sizes[4] / 2;

    int blocks = (N + LOC_THREADS - 1) / LOC_THREADS;     // 16
    // pair capacity: 7 pair warps per block
    int pairSlots = blocks * 7;
    if (pairSlots < P) blocks = (P + 6) / 7;              // safety (not hit here)

    float invN2 = 1.0f / ((float)N * (float)N);
    float pairScale = 0.5f / ((float)P + 1e-7f);

    dosa_split_kernel<<<blocks, TPB>>>(pred, tgt, emb, dens, idx, out,
                                       N, D, P, blocks, invN2, pairScale);
}

// round 8
// speedup vs baseline: 1.0332x; 1.0295x over previous
#include <cuda_runtime.h>
#include <math.h>

// ---------------------------------------------------------------------------
// DOSAConLoss — single-launch, dedicated-pair-warp, short-math version.
//
// loss_loc factorizes (reference broadcasts (N,1)/(N,) -> (N,N) mean):
//   loss_loc = (Sum_i dw_i*hw_i*(1-ciou_i)^2.5) * (Sum_j 1/(area_j+1e-7)) / N^2
//
// 16 blocks x 736 threads (23 warps):
//   warps 0-15 : loc, one box per thread (512 boxes/block, 8192 total)
//   warps 16-22: pair, one pair per warp (p = (w-16)*16 + blockIdx, 112>=100)
//
// Math cuts vs R7:
//   * atan(a)-atan(b) = atan((a-b)/(1+ab)) -> ONE atanf, ONE fast-div
//     (valid: a,b>0 so ab>0; |result| < pi/2 matches)
//   * sqrt(t) = t * rsqrt(t) (MUFU.RSQ), clamped to avoid 0*inf
//
// Reduction: warp shuffle -> fire-and-forget RED.ADD into 3 global scalars;
// __syncthreads + ONE acq_rel bump per block; last block finalizes + resets.
// ---------------------------------------------------------------------------

#define EPSF        1e-7f
#define ALPHA_C     1.2f
#define TAU_C       0.3f
#define DELTA_C     1.0f
#define FOUR_PI2    0.40528473456935108577f   // 4/pi^2

#define TPB         736          // 23 warps: 16 loc + 7 pair
#define LOC_THREADS 512

__device__ float g_accA = 0.0f;        // Σ dw*hw*(1-ciou)^2.5
__device__ float g_accB = 0.0f;        // Σ 1/(area+1e-7)
__device__ float g_accC = 0.0f;        // Σ masked pair loss
__device__ unsigned int g_done = 0;    // block completion counter

__device__ __forceinline__ unsigned int atomic_inc_acq_rel(unsigned int* p) {
    unsigned int prev;
    asm volatile("atom.acq_rel.gpu.add.u32 %0, [%1], 1;"
                 : "=r"(prev) : "l"(p) : "memory");
    return prev;
}

__device__ __forceinline__ float ld_acquire_f(const float* p) {
    float v;
    asm volatile("ld.acquire.gpu.f32 %0, [%1];" : "=f"(v) : "l"(p) : "memory");
    return v;
}

// fast sqrt for strictly non-negative t (uses MUFU.RSQ)
__device__ __forceinline__ float fast_sqrt_nn(float t) {
    float tc = fmaxf(t, 1e-30f);
    return t * __frsqrt_rn(tc);
}

__global__ __launch_bounds__(TPB)
void dosa_split_kernel(const float4* __restrict__ pred,
                       const float4* __restrict__ tgt,
                       const float*  __restrict__ emb,
                       const float*  __restrict__ dens,
                       const int2*   __restrict__ idx,
                       float* __restrict__ out,
                       int N, int D, int P, int nblocks,
                       float invN2, float pairScale) {
    int lane = threadIdx.x & 31;
    int warp = threadIdx.x >> 5;

    if (warp >= 16) {
        // ================= dedicated pair warps =================
        // Chain starts immediately: idx -> pred/emb gather -> reduce.
        int p = (warp - 16) * nblocks + blockIdx.x;
        if (p < P) {
            int2 ij = idx[p];
            int pi = ij.x, pj = ij.y;

            const float4* ei = (const float4*)(emb + (size_t)pi * D);
            const float4* ej = (const float4*)(emb + (size_t)pj * D);
            float4 bi = pred[pi];
            float4 bj = pred[pj];

            int D4 = D >> 2;                      // 64
            float s = 0.0f;
            for (int c = lane; c < D4; c += 32) { // 2 iterations at D=256
                float4 u = ei[c];
                float4 v = ej[c];
                float d0 = u.x - v.x, d1 = u.y - v.y;
                float d2 = u.z - v.z, d3 = u.w - v.w;
                s = fmaf(d0, d0, s); s = fmaf(d1, d1, s);
                s = fmaf(d2, d2, s); s = fmaf(d3, d3, s);
            }
            #pragma unroll
            for (int off = 16; off > 0; off >>= 1)
                s += __shfl_down_sync(0xffffffffu, s, off);

            if (lane == 0) {
                float a_x1 = bi.x - bi.z * 0.5f, a_x2 = bi.x + bi.z * 0.5f;
                float a_y1 = bi.y - bi.w * 0.5f, a_y2 = bi.y + bi.w * 0.5f;
                float b_x1 = bj.x - bj.z * 0.5f, b_x2 = bj.x + bj.z * 0.5f;
                float b_y1 = bj.y - bj.w * 0.5f, b_y2 = bj.y + bj.w * 0.5f;
                float iw = fmaxf(fminf(a_x2, b_x2) - fmaxf(a_x1, b_x1), 0.0f);
                float ih = fmaxf(fminf(a_y2, b_y2) - fmaxf(a_y1, b_y1), 0.0f);
                float inter = iw * ih;
                float uni = bi.z * bi.w + bj.z * bj.w - inter + EPSF;
                float piou = __fdividef(inter, uni);
                if (piou > TAU_C) {
                    float d = fast_sqrt_nn(s);
                    float t = fmaxf(DELTA_C - d, 0.0f);
                    if (t > 0.0f) atomicAdd(&g_accC, t * t);
                }
            }
        }
    } else {
        // ================= loc warps: one box per thread =================
        float accA = 0.0f, accB = 0.0f;
        int i = blockIdx.x * LOC_THREADS + threadIdx.x;
        if (i < N) {
            float4 b1 = pred[i];
            float4 b2 = tgt[i];
            float dv  = dens[i];

            float w1 = b1.z, h1 = b1.w, w2 = b2.z, h2 = b2.w;
            float b1x1 = b1.x - w1 * 0.5f, b1x2 = b1.x + w1 * 0.5f;
            float b1y1 = b1.y - h1 * 0.5f, b1y2 = b1.y + h1 * 0.5f;
            float b2x1 = b2.x - w2 * 0.5f, b2x2 = b2.x + w2 * 0.5f;
            float b2y1 = b2.y - h2 * 0.5f, b2y2 = b2.y + h2 * 0.5f;

            float iw = fmaxf(fminf(b1x2, b2x2) - fmaxf(b1x1, b2x1), 0.0f);
            float ih = fmaxf(fminf(b1y2, b2y2) - fmaxf(b1y1, b2y1), 0.0f);
            float inter = iw * ih;
            float uni   = w1 * h1 + w2 * h2 - inter + EPSF;
            float iou   = __fdividef(inter, uni);

            float cw = fmaxf(b1x2, b2x2) - fminf(b1x1, b2x1);
            float ch = fmaxf(b1y2, b2y2) - fminf(b1y1, b2y1);
            float c2 = cw * cw + ch * ch + EPSF;

            float dx = b2x1 + b2x2 - b1x1 - b1x2;
            float dy = b2y1 + b2y2 - b1y1 - b1y2;
            float rho2 = (dx * dx + dy * dy) * 0.25f;

            // atan(w2/h2) - atan(w1/h1) = atan((w2*h1 - w1*h2)/(h1*h2 + w1*w2))
            // (both args > 0 -> product > 0, identity exact in this range)
            float num = w2 * h1 - w1 * h2;
            float den = fmaf(h1, h2, w1 * w2);
            float dat = atanf(__fdividef(num, den));
            float v   = FOUR_PI2 * dat * dat;
            float alpha = __fdividef(v, v - iou + (1.0f + EPSF));
            float ciou = iou - (__fdividef(rho2, c2) + v * alpha);

            float t  = 1.0f - ciou;                   // >= 0
            float pw = t * t * fast_sqrt_nn(t);       // t^2.5
            float dw = fmaf(ALPHA_C, dv, 1.0f);
            float hw = __fdividef(1.0f, 1.0f + __expf(fmaf(5.0f, ciou, -2.5f)));
            accA = dw * hw * pw;
            accB = __fdividef(1.0f, fmaf(w2, h2, 1e-7f));
        }
        #pragma unroll
        for (int off = 16; off > 0; off >>= 1) {
            accA += __shfl_down_sync(0xffffffffu, accA, off);
            accB += __shfl_down_sync(0xffffffffu, accB, off);
        }
        if (lane == 0) {
            atomicAdd(&g_accA, accA);                 // RED.ADD (no return)
            atomicAdd(&g_accB, accB);
        }
    }

    // ---- block completion: hb edge from all warps, then ONE bump ----
    __syncthreads();
    if (threadIdx.x != 0) return;

    unsigned int prev = atomic_inc_acq_rel(&g_done);
    if (prev != (unsigned int)(nblocks - 1)) return;

    // last block: acquire-load the three scalars, combine, reset
    float a = ld_acquire_f(&g_accA);
    float b = ld_acquire_f(&g_accB);
    float c = ld_acquire_f(&g_accC);
    out[0] = a * b * invN2 + c * pairScale;
    g_accA = 0.0f;
    g_accB = 0.0f;
    g_accC = 0.0f;
    g_done = 0;                            // reset for next graph replay
}

extern "C" void kernel_launch(void* const* d_in, const int* in_sizes, int n_in,
                              void* d_out, int out_size) {
    const float4* pred = (const float4*)d_in[0];
    const float4* tgt  = (const float4*)d_in[1];
    const float*  emb  = (const float*)d_in[2];
    const float*  dens = (const float*)d_in[3];
    const int2*   idx  = (const int2*)d_in[4];
    float* out = (float*)d_out;

    int N = in_sizes[0] / 4;
    int D = in_sizes[2] / N;
    int P = in_sizes[4] / 2;

    int blocks = (N + LOC_THREADS - 1) / LOC_THREADS;     // 16
    int pairSlots = blocks * 7;
    if (pairSlots < P) blocks = (P + 6) / 7;              // safety (not hit here)

    float invN2 = 1.0f / ((float)N * (float)N);
    float pairScale = 0.5f / ((float)P + 1e-7f);

    dosa_split_kernel<<<blocks, TPB>>>(pred, tgt, emb, dens, idx, out,
                                       N, D, P, blocks, invN2, pairScale);
}

// round 9
// speedup vs baseline: 1.3462x; 1.3029x over previous
#include <cuda_runtime.h>
#include <math.h>

// ---------------------------------------------------------------------------
// DOSAConLoss — single-launch, dedicated-pair-warp, packed-accumulator version.
//
// loss_loc factorizes (reference broadcasts (N,1)/(N,) -> (N,N) mean):
//   loss_loc = (Sum_i dw_i*hw_i*(1-ciou_i)^2.5) * (Sum_j 1/(area_j+1e-7)) / N^2
//
// 16 blocks x 736 threads (23 warps):
//   warps 0-15 : loc, one box per thread (512 boxes/block, 8192 total)
//   warps 16-22: pair, one pair per warp (p = (w-16)*16 + blockIdx, 112>=100)
//
// Accumulators {A,B,C,done} live in ONE 16-byte sector. Warp shuffle ->
// fire-and-forget RED.ADD; __syncthreads + ONE acq_rel bump per block. The
// bump's acquire synchronizes with all blocks' release bumps, so the last
// block fetches A,B,C with a single plain v4 load (same sector as counter).
// ---------------------------------------------------------------------------

#define EPSF        1e-7f
#define ALPHA_C     1.2f
#define TAU_C       0.3f
#define DELTA_C     1.0f
#define FOUR_PI2    0.40528473456935108577f   // 4/pi^2

#define TPB         736          // 23 warps: 16 loc + 7 pair
#define LOC_THREADS 512

struct __align__(16) Acc {
    float accA;            // Σ dw*hw*(1-ciou)^2.5
    float accB;            // Σ 1/(area+1e-7)
    float accC;            // Σ masked pair loss
    unsigned int done;     // block completion counter
};
__device__ Acc g_acc = {0.0f, 0.0f, 0.0f, 0u};

__device__ __forceinline__ unsigned int atomic_inc_acq_rel(unsigned int* p) {
    unsigned int prev;
    asm volatile("atom.acq_rel.gpu.add.u32 %0, [%1], 1;"
                 : "=r"(prev) : "l"(p) : "memory");
    return prev;
}

// plain v4 load (ordering provided by the preceding acq_rel atomic)
__device__ __forceinline__ float4 ld_v4(const Acc* p) {
    float4 v;
    asm volatile("ld.global.v4.f32 {%0,%1,%2,%3}, [%4];"
                 : "=f"(v.x), "=f"(v.y), "=f"(v.z), "=f"(v.w)
                 : "l"(p) : "memory");
    return v;
}

__device__ __forceinline__ void st_v4(Acc* p, float4 v) {
    asm volatile("st.global.v4.f32 [%0], {%1,%2,%3,%4};"
                 :: "l"(p), "f"(v.x), "f"(v.y), "f"(v.z), "f"(v.w)
                 : "memory");
}

// fast sqrt for strictly non-negative t (uses MUFU.RSQ)
__device__ __forceinline__ float fast_sqrt_nn(float t) {
    float tc = fmaxf(t, 1e-30f);
    return t * __frsqrt_rn(tc);
}

__global__ __launch_bounds__(TPB)
void dosa_split_kernel(const float4* __restrict__ pred,
                       const float4* __restrict__ tgt,
                       const float*  __restrict__ emb,
                       const float*  __restrict__ dens,
                       const int2*   __restrict__ idx,
                       float* __restrict__ out,
                       int N, int D, int P, int nblocks,
                       float invN2, float pairScale) {
    int lane = threadIdx.x & 31;
    int warp = threadIdx.x >> 5;

    if (warp >= 16) {
        // ================= dedicated pair warps =================
        // Chain starts immediately: idx -> pred/emb gather -> reduce.
        int p = (warp - 16) * nblocks + blockIdx.x;
        if (p < P) {
            int2 ij = idx[p];
            int pi = ij.x, pj = ij.y;

            const float4* ei = (const float4*)(emb + (size_t)pi * D);
            const float4* ej = (const float4*)(emb + (size_t)pj * D);
            float4 bi = pred[pi];
            float4 bj = pred[pj];

            int D4 = D >> 2;                      // 64
            float s = 0.0f;
            for (int c = lane; c < D4; c += 32) { // 2 iterations at D=256
                float4 u = ei[c];
                float4 v = ej[c];
                float d0 = u.x - v.x, d1 = u.y - v.y;
                float d2 = u.z - v.z, d3 = u.w - v.w;
                s = fmaf(d0, d0, s); s = fmaf(d1, d1, s);
                s = fmaf(d2, d2, s); s = fmaf(d3, d3, s);
            }
            #pragma unroll
            for (int off = 16; off > 0; off >>= 1)
                s += __shfl_down_sync(0xffffffffu, s, off);

            if (lane == 0) {
                float a_x1 = bi.x - bi.z * 0.5f, a_x2 = bi.x + bi.z * 0.5f;
                float a_y1 = bi.y - bi.w * 0.5f, a_y2 = bi.y + bi.w * 0.5f;
                float b_x1 = bj.x - bj.z * 0.5f, b_x2 = bj.x + bj.z * 0.5f;
                float b_y1 = bj.y - bj.w * 0.5f, b_y2 = bj.y + bj.w * 0.5f;
                float iw = fmaxf(fminf(a_x2, b_x2) - fmaxf(a_x1, b_x1), 0.0f);
                float ih = fmaxf(fminf(a_y2, b_y2) - fmaxf(a_y1, b_y1), 0.0f);
                float inter = iw * ih;
                float uni = bi.z * bi.w + bj.z * bj.w - inter + EPSF;
                float piou = __fdividef(inter, uni);
                if (piou > TAU_C) {
                    float d = fast_sqrt_nn(s);
                    float t = fmaxf(DELTA_C - d, 0.0f);
                    if (t > 0.0f) atomicAdd(&g_acc.accC, t * t);
                }
            }
        }
    } else {
        // ================= loc warps: one box per thread =================
        float accA = 0.0f, accB = 0.0f;
        int i = blockIdx.x * LOC_THREADS + threadIdx.x;
        if (i < N) {
            float4 b1 = pred[i];
            float4 b2 = tgt[i];
            float dv  = dens[i];

            float w1 = b1.z, h1 = b1.w, w2 = b2.z, h2 = b2.w;
            float b1x1 = b1.x - w1 * 0.5f, b1x2 = b1.x + w1 * 0.5f;
            float b1y1 = b1.y - h1 * 0.5f, b1y2 = b1.y + h1 * 0.5f;
            float b2x1 = b2.x - w2 * 0.5f, b2x2 = b2.x + w2 * 0.5f;
            float b2y1 = b2.y - h2 * 0.5f, b2y2 = b2.y + h2 * 0.5f;

            float iw = fmaxf(fminf(b1x2, b2x2) - fmaxf(b1x1, b2x1), 0.0f);
            float ih = fmaxf(fminf(b1y2, b2y2) - fmaxf(b1y1, b2y1), 0.0f);
            float inter = iw * ih;
            float uni   = w1 * h1 + w2 * h2 - inter + EPSF;
            float iou   = __fdividef(inter, uni);

            float cw = fmaxf(b1x2, b2x2) - fminf(b1x1, b2x1);
            float ch = fmaxf(b1y2, b2y2) - fminf(b1y1, b2y1);
            float c2 = cw * cw + ch * ch + EPSF;

            float dx = b2x1 + b2x2 - b1x1 - b1x2;
            float dy = b2y1 + b2y2 - b1y1 - b1y2;
            float rho2 = (dx * dx + dy * dy) * 0.25f;

            // atan(w2/h2) - atan(w1/h1) = atan((w2*h1 - w1*h2)/(h1*h2 + w1*w2))
            float num = w2 * h1 - w1 * h2;
            float den = fmaf(h1, h2, w1 * w2);
            float dat = atanf(__fdividef(num, den));
            float v   = FOUR_PI2 * dat * dat;
            float alpha = __fdividef(v, v - iou + (1.0f + EPSF));
            float ciou = iou - (__fdividef(rho2, c2) + v * alpha);

            float t  = 1.0f - ciou;                   // >= 0
            float pw = t * t * fast_sqrt_nn(t);       // t^2.5
            float dw = fmaf(ALPHA_C, dv, 1.0f);
            float hw = __fdividef(1.0f, 1.0f + __expf(fmaf(5.0f, ciou, -2.5f)));
            accA = dw * hw * pw;
            accB = __fdividef(1.0f, fmaf(w2, h2, 1e-7f));
        }
        #pragma unroll
        for (int off = 16; off > 0; off >>= 1) {
            accA += __shfl_down_sync(0xffffffffu, accA, off);
            accB += __shfl_down_sync(0xffffffffu, accB, off);
        }
        if (lane == 0) {
            atomicAdd(&g_acc.accA, accA);             // RED.ADD (no return)
            atomicAdd(&g_acc.accB, accB);
        }
    }

    // ---- block completion: hb edge from all warps, then ONE bump ----
    __syncthreads();
    if (threadIdx.x != 0) return;

    unsigned int prev = atomic_inc_acq_rel(&g_acc.done);
    if (prev != (unsigned int)(nblocks - 1)) return;

    // last block: acq_rel bump above provides acquire ordering; one v4 load
    // fetches A,B,C from the same 16B sector the bump just touched.
    float4 abc = ld_v4(&g_acc);
    out[0] = abc.x * abc.y * invN2 + abc.z * pairScale;
    st_v4(&g_acc, make_float4(0.0f, 0.0f, 0.0f, 0.0f));  // reset for replay
}

extern "C" void kernel_launch(void* const* d_in, const int* in_sizes, int n_in,
                              void* d_out, int out_size) {
    const float4* pred = (const float4*)d_in[0];
    const float4* tgt  = (const float4*)d_in[1];
    const float*  emb  = (const float*)d_in[2];
    const float*  dens = (const float*)d_in[3];
    const int2*   idx  = (const int2*)d_in[4];
    float* out = (float*)d_out;

    int N = in_sizes[0] / 4;
    int D = in_sizes[2] / N;
    int P = in_sizes[4] / 2;

    int blocks = (N + LOC_THREADS - 1) / LOC_THREADS;     // 16
    int pairSlots = blocks * 7;
    if (pairSlots < P) blocks = (P + 6) / 7;              // safety (not hit here)

    float invN2 = 1.0f / ((float)N * (float)N);
    float pairScale = 0.5f / ((float)P + 1e-7f);

    dosa_split_kernel<<<blocks, TPB>>>(pred, tgt, emb, dens, idx, out,
                                       N, D, P, blocks, invN2, pairScale);
}